// round 14
// baseline (speedup 1.0000x reference)
#include <cuda_runtime.h>
#include <cstdint>
#include <math.h>
#include <float.h>

// Problem constants
#define B_SZ 128
#define C_SZ 1024
#define D_SZ 32000           // 8*250*16
#define D4   (D_SZ/4)
#define TOPK 5
#define TEMP 0.1f

// GEMM structure: K atoms of 32 floats, split-K
#define BKA    32
#define SPLITS 18             // 8 * 18 = 144 CTAs = 1 wave
#define NB     8              // N tiles of 128

// TS path: A hi/lo in TMEM (64 cols/stage), B hi/lo in smem (2 x 16KB/stage)
#define BTILE_BYTES 16384
#define STAGE_BYTES (2 * BTILE_BYTES)    // 32768 (Bh|Bl)
#define NSTAGE 3
#define DYN_SMEM (NSTAGE * STAGE_BYTES + 1024)   // 99328

// TMEM layout: stage s -> A-hi at s*64, A-lo at s*64+32; D at 192..319
#define TMEM_D_OFF 192

// fallback smem: pitch 36 floats (2 tiles = 36KB < DYN_SMEM)
#define PT 36
#define FB_TILE_FLOATS (128 * PT)

// idesc tf32: dtype=F32(1)<<4, atype=TF32(2)<<7, btype=TF32(2)<<10, N/8(16)<<17, M/16(8)<<24
#define MMA_IDESC 0x8200910u

// Output layout (float32): quantized | main_indices | main_distances | usage_new
#define OFF_Q     0
#define OFF_IDX   (B_SZ * D_SZ)
#define OFF_DIST  (OFF_IDX + B_SZ)
#define OFF_USAGE (OFF_DIST + B_SZ)

// Scratch (device globals — no allocation allowed)
__device__ float g_part[SPLITS][B_SZ * C_SZ];   // split-K partial dots
__device__ float g_cnp[SPLITS][C_SZ];           // codebook norm partials
__device__ float g_lnp[SPLITS][B_SZ];           // latent norm partials
__device__ float g_topw[B_SZ][8];
__device__ int   g_topi[B_SZ][8];

// Feature gate: tcgen05 exists only in the sm_103a compilation pass.
#if defined(__CUDA_ARCH__) && defined(__CUDA_ARCH_FEAT_SM103_ALL)
#define HAS_TCGEN05 1
#else
#define HAS_TCGEN05 0
#endif

// ---------------------------------------------------------------------------
// Common helpers
// ---------------------------------------------------------------------------
__device__ __forceinline__ uint32_t smem_u32(const void* p) {
    uint32_t a;
    asm("{ .reg .u64 t; cvta.to.shared.u64 t, %1; cvt.u32.u64 %0, t; }" : "=r"(a) : "l"(p));
    return a;
}
__device__ __forceinline__ void unpack2(unsigned long long v, float& x, float& y) {
    asm("mov.b64 {%0, %1}, %2;" : "=f"(x), "=f"(y) : "l"(v));
}
__device__ __forceinline__ void ffma2(unsigned long long& d,
                                      unsigned long long a,
                                      unsigned long long b) {
    asm("fma.rn.f32x2 %0, %1, %2, %3;" : "=l"(d) : "l"(a), "l"(b), "l"(d));
}

#if HAS_TCGEN05
// ---------------------------------------------------------------------------
// tcgen05 / mbarrier helpers (sm_103a pass only)
// ---------------------------------------------------------------------------
__device__ __forceinline__ bool elect1() {
    uint32_t p;
    asm volatile("{ .reg .pred p; elect.sync _|p, 0xFFFFFFFF; selp.b32 %0, 1, 0, p; }" : "=r"(p));
    return p != 0;
}
__device__ __forceinline__ void mbar_init(uint32_t mbar, uint32_t cnt) {
    asm volatile("mbarrier.init.shared.b64 [%0], %1;" :: "r"(mbar), "r"(cnt) : "memory");
}
__device__ __forceinline__ void mbar_arrive(uint32_t mbar) {
    asm volatile("mbarrier.arrive.shared.b64 _, [%0];" :: "r"(mbar) : "memory");
}
__device__ __forceinline__ void mbar_wait(uint32_t mbar, uint32_t parity) {
    asm volatile("{\n\t.reg .pred P;\n\t"
                 "WL_%=:\n\t"
                 "mbarrier.try_wait.parity.acquire.cta.shared::cta.b64 P, [%0], %1, 0x989680;\n\t"
                 "@P bra.uni WD_%=;\n\t"
                 "bra.uni WL_%=;\n\t"
                 "WD_%=:\n\t}"
                 :: "r"(mbar), "r"(parity) : "memory");
}
__device__ __forceinline__ void tmem_alloc(uint32_t dst_smem, uint32_t ncols) {
    asm volatile("tcgen05.alloc.cta_group::1.sync.aligned.shared::cta.b32 [%0], %1;"
                 :: "r"(dst_smem), "r"(ncols) : "memory");
}
__device__ __forceinline__ void tmem_relinquish() {
    asm volatile("tcgen05.relinquish_alloc_permit.cta_group::1.sync.aligned;");
}
__device__ __forceinline__ void tmem_dealloc(uint32_t tmem, uint32_t ncols) {
    asm volatile("tcgen05.dealloc.cta_group::1.sync.aligned.b32 %0, %1;" :: "r"(tmem), "r"(ncols));
}
__device__ __forceinline__ void mma_commit(uint32_t mbar) {
    asm volatile("tcgen05.commit.cta_group::1.mbarrier::arrive::one.shared::cluster.b64 [%0];"
                 :: "r"(mbar) : "memory");
}
// TS form: A operand in TMEM
__device__ __forceinline__ void mma_tf32_ts(uint32_t d, uint32_t a_tmem, uint64_t bd, uint32_t en) {
    asm volatile("{\n\t.reg .pred p;\n\tsetp.ne.u32 p, %4, 0;\n\t"
                 "tcgen05.mma.cta_group::1.kind::tf32 [%0], [%1], %2, %3, {%5, %5, %5, %5}, p;\n\t}"
                 :: "r"(d), "r"(a_tmem), "l"(bd), "r"(MMA_IDESC), "r"(en), "r"(0u)
                 : "memory");
}
// SW128 K-major descriptor: layout=2(SW128), version=1, SBO=64, LBO=1
__device__ __forceinline__ uint64_t smem_desc(uint32_t addr) {
    return ((uint64_t)2 << 61) | ((uint64_t)1 << 46) | ((uint64_t)64 << 32) |
           ((uint64_t)1 << 16) | ((uint64_t)(addr >> 4) & 0x3FFF);
}
__device__ __forceinline__ uint32_t sw128(uint32_t off) { return off ^ ((off >> 3) & 0x70u); }

#define STTM_X32(addr, r)                                                          \
    asm volatile("tcgen05.st.sync.aligned.32x32b.x32.b32 [%0], "                   \
        "{%1, %2, %3, %4, %5, %6, %7, %8, %9, %10, %11, %12, %13, %14, %15, %16, " \
        " %17, %18, %19, %20, %21, %22, %23, %24, %25, %26, %27, %28, %29, %30, %31, %32};" \
        :: "r"(addr),                                                              \
           "r"((r)[0]),  "r"((r)[1]),  "r"((r)[2]),  "r"((r)[3]),                  \
           "r"((r)[4]),  "r"((r)[5]),  "r"((r)[6]),  "r"((r)[7]),                  \
           "r"((r)[8]),  "r"((r)[9]),  "r"((r)[10]), "r"((r)[11]),                 \
           "r"((r)[12]), "r"((r)[13]), "r"((r)[14]), "r"((r)[15]),                 \
           "r"((r)[16]), "r"((r)[17]), "r"((r)[18]), "r"((r)[19]),                 \
           "r"((r)[20]), "r"((r)[21]), "r"((r)[22]), "r"((r)[23]),                 \
           "r"((r)[24]), "r"((r)[25]), "r"((r)[26]), "r"((r)[27]),                 \
           "r"((r)[28]), "r"((r)[29]), "r"((r)[30]), "r"((r)[31])                  \
        : "memory")

#define LDTM_X32(r, addr)                                                          \
    asm volatile("tcgen05.ld.sync.aligned.32x32b.x32.b32 "                         \
        "{%0, %1, %2, %3, %4, %5, %6, %7, %8, %9, %10, %11, %12, %13, %14, %15, "  \
        " %16, %17, %18, %19, %20, %21, %22, %23, %24, %25, %26, %27, %28, %29, %30, %31}, [%32];" \
        : "=r"((r)[0]), "=r"((r)[1]), "=r"((r)[2]), "=r"((r)[3]),                  \
          "=r"((r)[4]), "=r"((r)[5]), "=r"((r)[6]), "=r"((r)[7]),                  \
          "=r"((r)[8]), "=r"((r)[9]), "=r"((r)[10]), "=r"((r)[11]),                \
          "=r"((r)[12]), "=r"((r)[13]), "=r"((r)[14]), "=r"((r)[15]),              \
          "=r"((r)[16]), "=r"((r)[17]), "=r"((r)[18]), "=r"((r)[19]),              \
          "=r"((r)[20]), "=r"((r)[21]), "=r"((r)[22]), "=r"((r)[23]),              \
          "=r"((r)[24]), "=r"((r)[25]), "=r"((r)[26]), "=r"((r)[27]),              \
          "=r"((r)[28]), "=r"((r)[29]), "=r"((r)[30]), "=r"((r)[31])               \
        : "r"(addr))
#endif // HAS_TCGEN05

// ---------------------------------------------------------------------------
// GEMM: grid (NB, SPLITS), 256 threads.
// sm_103a pass: tcgen05 tf32 TS-mode (A hi/lo in TMEM via STTM; B hi/lo in
//   smem). Warp-specialized producers: warps 0-3 = A rows, warps 4-7 = B rows.
//   Async full/empty mbarrier pipeline, 8 elected arrivals per stage.
// base pass (never selected at runtime): simple FFMA2 fallback.
// ---------------------------------------------------------------------------
__global__ __launch_bounds__(256, 1)
void gemm_kernel(const float* __restrict__ A,   // latent  [128][32000]
                 const float* __restrict__ Bm,  // codebook[1024][32000]
                 const float* __restrict__ usage_in,
                 float* __restrict__ usage_out)
{
    extern __shared__ float dynf[];
    const int t  = threadIdx.x;
    const int bx = blockIdx.x;
    const int s  = blockIdx.y;
    const int n0 = bx * 128;
    // uneven split: 1000 atoms of 32 = 18*55 + 10; splits 0..9 get 56
    const int tile0 = s * 55 + min(s, 10);
    const int ntile = 55 + (s < 10 ? 1 : 0);

    // usage copy (ordered before topk's atomics by stream order)
    if (bx == 0 && s == 0)
        ((float4*)usage_out)[t] = ((const float4*)usage_in)[t];

#if HAS_TCGEN05
    // ===================== tcgen05 tf32 TS async path ======================
    __shared__ uint32_t s_tmem;
    __shared__ __align__(8) unsigned long long s_full[NSTAGE];
    __shared__ __align__(8) unsigned long long s_empty[NSTAGE];
    const int wid  = t >> 5;
    const int lane = t & 31;

    char* bp = (char*)(((uintptr_t)dynf + 1023) & ~(uintptr_t)1023);
    const uint32_t base = smem_u32(bp);
    const uint32_t tmem_ptr_addr = smem_u32(&s_tmem);
    uint32_t mbF[NSTAGE], mbE[NSTAGE];
#pragma unroll
    for (int i = 0; i < NSTAGE; i++) {
        mbF[i] = smem_u32(&s_full[i]);
        mbE[i] = smem_u32(&s_empty[i]);
    }

    if (wid == 0) {
        tmem_alloc(tmem_ptr_addr, 512);
        tmem_relinquish();
    }
    if (t == 0) {
#pragma unroll
        for (int i = 0; i < NSTAGE; i++) {
            mbar_init(mbF[i], 8);     // one elected arrival per warp
            mbar_init(mbE[i], 1);     // MMA commit arrives
        }
    }
    __syncthreads();
    uint32_t tmem;
    asm volatile("ld.shared.b32 %0, [%1];" : "=r"(tmem) : "r"(tmem_ptr_addr));

    const bool isA = (wid < 4);
    const int row  = t & 127;            // A row (warps 0-3) or B row (warps 4-7)
    const uint32_t warp_off = (uint32_t)(wid & 3) << 21;   // TMEM subpartition

    const float* src = isA ? (A + (size_t)row * D_SZ)
                           : (Bm + (size_t)(n0 + row) * D_SZ);
    uint32_t stsOff[8];
#pragma unroll
    for (int q = 0; q < 8; q++)
        stsOff[q] = sw128((uint32_t)row * 128u + (uint32_t)q * 16u);

    float nrm = 0.f;

    for (int it = 0; it < ntile; it++) {
        const int stg = it % NSTAGE;
        const int k0 = (tile0 + it) * BKA;

        // LDG this tile's row segment (32 floats)
        float4 v4[8];
        const float4* s4 = (const float4*)(src + k0);
#pragma unroll
        for (int q = 0; q < 8; q++) v4[q] = s4[q];

        // wait stage free: commit of (it - NSTAGE) done
        if (it >= NSTAGE) mbar_wait(mbE[stg], ((it - NSTAGE) / NSTAGE) & 1);

        if (isA) {
            // split into hi/lo and STTM into stage TMEM columns
            uint32_t hi[32], lo[32];
#pragma unroll
            for (int q = 0; q < 8; q++) {
                float4 v = v4[q];
                if (bx == 0) nrm += v.x * v.x + v.y * v.y + v.z * v.z + v.w * v.w;
                uint32_t hx = __float_as_uint(v.x) & 0xFFFFE000u;
                uint32_t hy = __float_as_uint(v.y) & 0xFFFFE000u;
                uint32_t hz = __float_as_uint(v.z) & 0xFFFFE000u;
                uint32_t hw = __float_as_uint(v.w) & 0xFFFFE000u;
                hi[4 * q + 0] = hx; lo[4 * q + 0] = __float_as_uint(v.x - __uint_as_float(hx));
                hi[4 * q + 1] = hy; lo[4 * q + 1] = __float_as_uint(v.y - __uint_as_float(hy));
                hi[4 * q + 2] = hz; lo[4 * q + 2] = __float_as_uint(v.z - __uint_as_float(hz));
                hi[4 * q + 3] = hw; lo[4 * q + 3] = __float_as_uint(v.w - __uint_as_float(hw));
            }
            STTM_X32(tmem + stg * 64 + warp_off, hi);
            STTM_X32(tmem + stg * 64 + 32 + warp_off, lo);
            asm volatile("tcgen05.wait::st.sync.aligned;" ::: "memory");
        } else {
            // split into hi/lo and STS into stage smem tiles (SW128)
            char* sb = bp + stg * STAGE_BYTES;
#pragma unroll
            for (int q = 0; q < 8; q++) {
                float4 v = v4[q], h, l;
                nrm += v.x * v.x + v.y * v.y + v.z * v.z + v.w * v.w;
                h.x = __uint_as_float(__float_as_uint(v.x) & 0xFFFFE000u); l.x = v.x - h.x;
                h.y = __uint_as_float(__float_as_uint(v.y) & 0xFFFFE000u); l.y = v.y - h.y;
                h.z = __uint_as_float(__float_as_uint(v.z) & 0xFFFFE000u); l.z = v.z - h.z;
                h.w = __uint_as_float(__float_as_uint(v.w) & 0xFFFFE000u); l.w = v.w - h.w;
                *(float4*)(sb + stsOff[q]) = h;
                *(float4*)(sb + BTILE_BYTES + stsOff[q]) = l;
            }
        }
        __syncwarp();
        if (elect1()) mbar_arrive(mbF[stg]);

        // MMA-issue thread: consume this stage when all 8 warps arrived
        if (wid == 0 && elect1()) {
            mbar_wait(mbF[stg], (it / NSTAGE) & 1);
            asm volatile("fence.proxy.async.shared::cta;" ::: "memory");
            uint32_t sbu = base + stg * STAGE_BYTES;
            uint64_t dBh = smem_desc(sbu);
            uint64_t dBl = smem_desc(sbu + BTILE_BYTES);
            uint32_t aH = tmem + stg * 64;
            uint32_t aL = tmem + stg * 64 + 32;
#pragma unroll
            for (int k = 0; k < 4; k++)
                mma_tf32_ts(tmem + TMEM_D_OFF, aH + 8 * k, dBh + 2 * k, (it > 0) || (k > 0));
#pragma unroll
            for (int k = 0; k < 4; k++)
                mma_tf32_ts(tmem + TMEM_D_OFF, aH + 8 * k, dBl + 2 * k, 1u);
#pragma unroll
            for (int k = 0; k < 4; k++)
                mma_tf32_ts(tmem + TMEM_D_OFF, aL + 8 * k, dBh + 2 * k, 1u);
            mma_commit(mbE[stg]);
        }
    }

    // drain: tcgen05 ops complete in order -> last commit implies all done
    mbar_wait(mbE[(ntile - 1) % NSTAGE], ((ntile - 1) / NSTAGE) & 1);
    asm volatile("tcgen05.fence::after_thread_sync;" ::: "memory");
    __syncthreads();

    // norm writeout (one thread per row)
    if (isA) {
        if (bx == 0) g_lnp[s][row] = nrm;
    } else {
        g_cnp[s][n0 + row] = nrm;
    }

    // epilogue: TMEM D -> g_part.  warps 0-3: cols 0-63, warps 4-7: cols 64-127
    {
        const int colb = (wid >> 2) * 64;
        const int m = (wid & 3) * 32 + lane;
        float* dst = &g_part[s][(size_t)m * C_SZ + n0 + colb];
        uint32_t dr[32];
        LDTM_X32(dr, tmem + TMEM_D_OFF + colb);
        asm volatile("tcgen05.wait::ld.sync.aligned;" ::: "memory");
#pragma unroll
        for (int j = 0; j < 8; j++)
            ((float4*)dst)[j] = make_float4(__uint_as_float(dr[4 * j + 0]), __uint_as_float(dr[4 * j + 1]),
                                            __uint_as_float(dr[4 * j + 2]), __uint_as_float(dr[4 * j + 3]));
        LDTM_X32(dr, tmem + TMEM_D_OFF + colb + 32);
        asm volatile("tcgen05.wait::ld.sync.aligned;" ::: "memory");
#pragma unroll
        for (int j = 0; j < 8; j++)
            ((float4*)(dst + 32))[j] = make_float4(__uint_as_float(dr[4 * j + 0]), __uint_as_float(dr[4 * j + 1]),
                                                   __uint_as_float(dr[4 * j + 2]), __uint_as_float(dr[4 * j + 3]));
    }
    __syncthreads();
    if (wid == 0) tmem_dealloc(tmem, 512);

#else
    // ======= FFMA2 fallback (base pass; never selected at runtime) =========
    float* As = dynf;                       // 128 x PT
    float* Bs = dynf + FB_TILE_FLOATS;      // 128 x PT

    const int row  = t >> 1;
    const int half = t & 1;
    const int ty   = t >> 4;
    const int tx   = t & 15;

    const float* aSrc = A  + (size_t)row * D_SZ + half * 16;
    const float* bSrc = Bm + (size_t)(n0 + row) * D_SZ + half * 16;

    unsigned long long acc[8][8];
#pragma unroll
    for (int i = 0; i < 8; i++)
#pragma unroll
        for (int j = 0; j < 8; j++) acc[i][j] = 0ULL;

    float nb = 0.f, na = 0.f;

    for (int it = 0; it < ntile; it++) {
        const int k0 = (tile0 + it) * BKA;
        const float4* a4 = (const float4*)(aSrc + k0);
        const float4* b4 = (const float4*)(bSrc + k0);
        float4 a0 = a4[0], a1 = a4[1], a2v = a4[2], a3v = a4[3];
        float4 b0 = b4[0], b1 = b4[1], b2v = b4[2], b3v = b4[3];
        if (bx == 0) {
            na += a0.x * a0.x + a0.y * a0.y + a0.z * a0.z + a0.w * a0.w
                + a1.x * a1.x + a1.y * a1.y + a1.z * a1.z + a1.w * a1.w
                + a2v.x * a2v.x + a2v.y * a2v.y + a2v.z * a2v.z + a2v.w * a2v.w
                + a3v.x * a3v.x + a3v.y * a3v.y + a3v.z * a3v.z + a3v.w * a3v.w;
        }
        nb += b0.x * b0.x + b0.y * b0.y + b0.z * b0.z + b0.w * b0.w
            + b1.x * b1.x + b1.y * b1.y + b1.z * b1.z + b1.w * b1.w
            + b2v.x * b2v.x + b2v.y * b2v.y + b2v.z * b2v.z + b2v.w * b2v.w
            + b3v.x * b3v.x + b3v.y * b3v.y + b3v.z * b3v.z + b3v.w * b3v.w;
        float* ad = As + row * PT + half * 16;
        float* bd = Bs + row * PT + half * 16;
        *(float4*)(ad)      = a0;  *(float4*)(ad + 4)  = a1;
        *(float4*)(ad + 8)  = a2v; *(float4*)(ad + 12) = a3v;
        *(float4*)(bd)      = b0;  *(float4*)(bd + 4)  = b1;
        *(float4*)(bd + 8)  = b2v; *(float4*)(bd + 12) = b3v;
        __syncthreads();

#pragma unroll
        for (int k4 = 0; k4 < 8; k4++) {
            ulonglong2 a2[8];
#pragma unroll
            for (int i = 0; i < 8; i++)
                a2[i] = *(const ulonglong2*)(As + (ty + 16 * i) * PT + k4 * 4);
            ulonglong2 b2[8];
#pragma unroll
            for (int j = 0; j < 8; j++)
                b2[j] = *(const ulonglong2*)(Bs + (tx + 16 * j) * PT + k4 * 4);
#pragma unroll
            for (int i = 0; i < 8; i++)
#pragma unroll
                for (int j = 0; j < 8; j++) {
                    ffma2(acc[i][j], a2[i].x, b2[j].x);
                    ffma2(acc[i][j], a2[i].y, b2[j].y);
                }
        }
        __syncthreads();
    }

    nb += __shfl_xor_sync(0xFFFFFFFFu, nb, 1);
    if (half == 0) g_cnp[s][n0 + row] = nb;
    if (bx == 0) {
        na += __shfl_xor_sync(0xFFFFFFFFu, na, 1);
        if (half == 0) g_lnp[s][row] = na;
    }

    float* op = g_part[s];
#pragma unroll
    for (int i = 0; i < 8; i++) {
        const int m = ty + 16 * i;
#pragma unroll
        for (int j = 0; j < 8; j++) {
            float lo, hi;
            unpack2(acc[i][j], lo, hi);
            op[(size_t)m * C_SZ + n0 + tx + 16 * j] = lo + hi;
        }
    }
#endif
}

// ---------------------------------------------------------------------------
// Per-row: reduce partials (+ inline norm sums) -> dist, top-5 (lowest-index
// tie-break), softmax, outputs, usage scatter-add, stash for quantize.
// ---------------------------------------------------------------------------
__global__ void topk_kernel(float* __restrict__ out) {
    const int b   = blockIdx.x;
    const int tid = threadIdx.x;

    __shared__ float sd[C_SZ];
    __shared__ float rv[256];
    __shared__ int   ri[256];
    __shared__ float topd[TOPK];
    __shared__ int   topi[TOPK];
    __shared__ float s_ln;

    if (tid == 0) {
        float v = 0.f;
#pragma unroll
        for (int s = 0; s < SPLITS; s++) v += g_lnp[s][b];
        s_ln = v;
    }
    __syncthreads();
    const float ln = s_ln;

    for (int c = tid; c < C_SZ; c += 256) {
        float dot = 0.f, cn = 0.f;
#pragma unroll
        for (int s = 0; s < SPLITS; s++) {
            dot += g_part[s][b * C_SZ + c];
            cn  += g_cnp[s][c];
        }
        float d2 = ln + cn - 2.f * dot;
        sd[c] = sqrtf(fmaxf(d2, 0.f));
    }
    __syncthreads();

    for (int k = 0; k < TOPK; k++) {
        float best = FLT_MAX;
        int   bi   = C_SZ;
        for (int c = tid; c < C_SZ; c += 256) {
            float d = sd[c];
            if (d < best || (d == best && c < bi)) { best = d; bi = c; }
        }
        rv[tid] = best; ri[tid] = bi;
        __syncthreads();
        for (int s = 128; s > 0; s >>= 1) {
            if (tid < s) {
                float o = rv[tid + s]; int oi = ri[tid + s];
                if (o < rv[tid] || (o == rv[tid] && oi < ri[tid])) {
                    rv[tid] = o; ri[tid] = oi;
                }
            }
            __syncthreads();
        }
        if (tid == 0) {
            topd[k] = rv[0];
            topi[k] = ri[0];
            sd[ri[0]] = FLT_MAX;
        }
        __syncthreads();
    }

    if (tid == 0) {
        float m0 = topd[0];
        float e[TOPK], ssum = 0.f;
#pragma unroll
        for (int k = 0; k < TOPK; k++) {
            e[k] = expf(-(topd[k] - m0) / TEMP);
            ssum += e[k];
        }
        float inv = 1.f / ssum;
        out[OFF_IDX  + b] = (float)topi[0];
        out[OFF_DIST + b] = topd[0];
#pragma unroll
        for (int k = 0; k < TOPK; k++) {
            float w = e[k] * inv;
            atomicAdd(&out[OFF_USAGE + topi[k]], w);
            g_topw[b][k] = w;
            g_topi[b][k] = topi[k];
        }
    }
}

// ---------------------------------------------------------------------------
// quantized[b] = sum_k w[b][k] * codebook[idx[b][k]]   grid (B, 16 chunks)
// ---------------------------------------------------------------------------
__global__ void quant_kernel(const float* __restrict__ codebook,
                             float* __restrict__ out) {
    const int b     = blockIdx.x;
    const int chunk = blockIdx.y;
    const int tid   = threadIdx.x;
    __shared__ int   si[TOPK];
    __shared__ float sw[TOPK];
    if (tid < TOPK) { si[tid] = g_topi[b][tid]; sw[tid] = g_topw[b][tid]; }
    __syncthreads();

    const float4* cb = (const float4*)codebook;
    float4* outq = (float4*)(out + OFF_Q) + (size_t)b * D4;

    const float4* r0 = cb + (size_t)si[0] * D4;
    const float4* r1 = cb + (size_t)si[1] * D4;
    const float4* r2 = cb + (size_t)si[2] * D4;
    const float4* r3 = cb + (size_t)si[3] * D4;
    const float4* r4 = cb + (size_t)si[4] * D4;
    const float w0 = sw[0], w1 = sw[1], w2 = sw[2], w3 = sw[3], w4 = sw[4];

    const int p0 = chunk * (D4 / 16);
    const int p1 = p0 + (D4 / 16);
    for (int p = p0 + tid; p < p1; p += 256) {
        float4 v0 = r0[p], v1 = r1[p], v2 = r2[p], v3 = r3[p], v4 = r4[p];
        float4 r;
        r.x = w0 * v0.x + w1 * v1.x + w2 * v2.x + w3 * v3.x + w4 * v4.x;
        r.y = w0 * v0.y + w1 * v1.y + w2 * v2.y + w3 * v3.y + w4 * v4.y;
        r.z = w0 * v0.z + w1 * v1.z + w2 * v2.z + w3 * v3.z + w4 * v4.z;
        r.w = w0 * v0.w + w1 * v1.w + w2 * v2.w + w3 * v3.w + w4 * v4.w;
        outq[p] = r;
    }
}

// ---------------------------------------------------------------------------
extern "C" void kernel_launch(void* const* d_in, const int* in_sizes, int n_in,
                              void* d_out, int out_size) {
    const float* latent   = (const float*)d_in[0];
    const float* codebook = (const float*)d_in[1];
    const float* usage    = (const float*)d_in[2];
    float* out = (float*)d_out;

    cudaFuncSetAttribute((const void*)gemm_kernel,
                         cudaFuncAttributeMaxDynamicSharedMemorySize, DYN_SMEM);
    gemm_kernel<<<dim3(NB, SPLITS), 256, DYN_SMEM>>>(latent, codebook,
                                                     usage, out + OFF_USAGE);
    topk_kernel<<<B_SZ, 256>>>(out);
    quant_kernel<<<dim3(B_SZ, 16), 256>>>(codebook, out);
}

// round 15
// speedup vs baseline: 1.3495x; 1.3495x over previous
#include <cuda_runtime.h>
#include <cstdint>
#include <math.h>
#include <float.h>

// Problem constants
#define B_SZ 128
#define C_SZ 1024
#define D_SZ 32000           // 8*250*16
#define D4   (D_SZ/4)
#define TOPK 5
#define TEMP 0.1f

// GEMM structure: K atoms of 32 floats (128B rows, SW128), split-K
#define BKA    32
#define SPLITS 18             // 8 * 18 = 144 CTAs = 1 wave
#define NB     8              // N tiles of 128

// tensor path smem: per stage Ah|Al|Bh|Bl tiles of 128 x 128B
#define TILE_BYTES  16384
#define STAGE_BYTES (4 * TILE_BYTES)     // 65536
#define NSTAGE 3
#define DYN_SMEM (NSTAGE * STAGE_BYTES + 1024)   // 197632

// fallback smem: pitch 36 floats
#define PT 36
#define FB_TILE_FLOATS (128 * PT)

// idesc tf32: dtype=F32(1)<<4, atype=TF32(2)<<7, btype=TF32(2)<<10, N/8(16)<<17, M/16(8)<<24
#define MMA_IDESC 0x8200910u

// Output layout (float32): quantized | main_indices | main_distances | usage_new
#define OFF_Q     0
#define OFF_IDX   (B_SZ * D_SZ)
#define OFF_DIST  (OFF_IDX + B_SZ)
#define OFF_USAGE (OFF_DIST + B_SZ)

// Scratch (device globals — no allocation allowed)
__device__ float g_part[SPLITS][B_SZ * C_SZ];   // split-K partial dots
__device__ float g_cnp[SPLITS][C_SZ];           // codebook norm partials
__device__ float g_lnp[SPLITS][B_SZ];           // latent norm partials
__device__ float g_topw[B_SZ][8];
__device__ int   g_topi[B_SZ][8];

// Feature gate: tcgen05 exists only in the sm_103a compilation pass.
#if defined(__CUDA_ARCH__) && defined(__CUDA_ARCH_FEAT_SM103_ALL)
#define HAS_TCGEN05 1
#else
#define HAS_TCGEN05 0
#endif

// ---------------------------------------------------------------------------
// Common helpers
// ---------------------------------------------------------------------------
__device__ __forceinline__ uint32_t smem_u32(const void* p) {
    uint32_t a;
    asm("{ .reg .u64 t; cvta.to.shared.u64 t, %1; cvt.u32.u64 %0, t; }" : "=r"(a) : "l"(p));
    return a;
}
__device__ __forceinline__ void unpack2(unsigned long long v, float& x, float& y) {
    asm("mov.b64 {%0, %1}, %2;" : "=f"(x), "=f"(y) : "l"(v));
}
__device__ __forceinline__ void ffma2(unsigned long long& d,
                                      unsigned long long a,
                                      unsigned long long b) {
    asm("fma.rn.f32x2 %0, %1, %2, %3;" : "=l"(d) : "l"(a), "l"(b), "l"(d));
}

#if HAS_TCGEN05
// ---------------------------------------------------------------------------
// tcgen05 / mbarrier helpers (sm_103a pass only)
// ---------------------------------------------------------------------------
__device__ __forceinline__ bool elect1() {
    uint32_t p;
    asm volatile("{ .reg .pred p; elect.sync _|p, 0xFFFFFFFF; selp.b32 %0, 1, 0, p; }" : "=r"(p));
    return p != 0;
}
__device__ __forceinline__ void mbar_init(uint32_t mbar, uint32_t cnt) {
    asm volatile("mbarrier.init.shared.b64 [%0], %1;" :: "r"(mbar), "r"(cnt) : "memory");
}
__device__ __forceinline__ void mbar_wait(uint32_t mbar, uint32_t parity) {
    asm volatile("{\n\t.reg .pred P;\n\t"
                 "WL_%=:\n\t"
                 "mbarrier.try_wait.parity.acquire.cta.shared::cta.b64 P, [%0], %1, 0x989680;\n\t"
                 "@P bra.uni WD_%=;\n\t"
                 "bra.uni WL_%=;\n\t"
                 "WD_%=:\n\t}"
                 :: "r"(mbar), "r"(parity) : "memory");
}
__device__ __forceinline__ void tmem_alloc(uint32_t dst_smem, uint32_t ncols) {
    asm volatile("tcgen05.alloc.cta_group::1.sync.aligned.shared::cta.b32 [%0], %1;"
                 :: "r"(dst_smem), "r"(ncols) : "memory");
}
__device__ __forceinline__ void tmem_relinquish() {
    asm volatile("tcgen05.relinquish_alloc_permit.cta_group::1.sync.aligned;");
}
__device__ __forceinline__ void tmem_dealloc(uint32_t tmem, uint32_t ncols) {
    asm volatile("tcgen05.dealloc.cta_group::1.sync.aligned.b32 %0, %1;" :: "r"(tmem), "r"(ncols));
}
__device__ __forceinline__ void mma_commit(uint32_t mbar) {
    asm volatile("tcgen05.commit.cta_group::1.mbarrier::arrive::one.shared::cluster.b64 [%0];"
                 :: "r"(mbar) : "memory");
}
__device__ __forceinline__ void mma_tf32_ss(uint32_t d, uint64_t ad, uint64_t bd, uint32_t en) {
    asm volatile("{\n\t.reg .pred p;\n\tsetp.ne.u32 p, %4, 0;\n\t"
                 "tcgen05.mma.cta_group::1.kind::tf32 [%0], %1, %2, %3, {%5, %5, %5, %5}, p;\n\t}"
                 :: "r"(d), "l"(ad), "l"(bd), "r"(MMA_IDESC), "r"(en), "r"(0u)
                 : "memory");
}
// SW128 K-major descriptor: layout=2(SW128), version=1, SBO=64, LBO=1
__device__ __forceinline__ uint64_t smem_desc(uint32_t addr) {
    return ((uint64_t)2 << 61) | ((uint64_t)1 << 46) | ((uint64_t)64 << 32) |
           ((uint64_t)1 << 16) | ((uint64_t)(addr >> 4) & 0x3FFF);
}
__device__ __forceinline__ uint32_t sw128(uint32_t off) { return off ^ ((off >> 3) & 0x70u); }

#define LDTM_X32(r, addr)                                                          \
    asm volatile("tcgen05.ld.sync.aligned.32x32b.x32.b32 "                         \
        "{%0, %1, %2, %3, %4, %5, %6, %7, %8, %9, %10, %11, %12, %13, %14, %15, "  \
        " %16, %17, %18, %19, %20, %21, %22, %23, %24, %25, %26, %27, %28, %29, %30, %31}, [%32];" \
        : "=r"((r)[0]), "=r"((r)[1]), "=r"((r)[2]), "=r"((r)[3]),                  \
          "=r"((r)[4]), "=r"((r)[5]), "=r"((r)[6]), "=r"((r)[7]),                  \
          "=r"((r)[8]), "=r"((r)[9]), "=r"((r)[10]), "=r"((r)[11]),                \
          "=r"((r)[12]), "=r"((r)[13]), "=r"((r)[14]), "=r"((r)[15]),              \
          "=r"((r)[16]), "=r"((r)[17]), "=r"((r)[18]), "=r"((r)[19]),              \
          "=r"((r)[20]), "=r"((r)[21]), "=r"((r)[22]), "=r"((r)[23]),              \
          "=r"((r)[24]), "=r"((r)[25]), "=r"((r)[26]), "=r"((r)[27]),              \
          "=r"((r)[28]), "=r"((r)[29]), "=r"((r)[30]), "=r"((r)[31])               \
        : "r"(addr))
#endif // HAS_TCGEN05

// ---------------------------------------------------------------------------
// GEMM: grid (NB, SPLITS), 256 threads.
// sm_103a pass: tcgen05 tf32 (3xTF32), SW128 tiles, NSTAGE=3 ring — the R9
//   structure, plus REGISTER DOUBLE-BUFFER PREFETCH: tile it+1's LDGs issue
//   before the wait/split of tile it, hiding global-load latency.
// base pass (never selected at runtime): simple FFMA2 fallback.
// ---------------------------------------------------------------------------
__global__ __launch_bounds__(256, 1)
void gemm_kernel(const float* __restrict__ A,   // latent  [128][32000]
                 const float* __restrict__ Bm,  // codebook[1024][32000]
                 const float* __restrict__ usage_in,
                 float* __restrict__ usage_out)
{
    extern __shared__ float dynf[];
    const int t  = threadIdx.x;
    const int bx = blockIdx.x;
    const int s  = blockIdx.y;
    const int n0 = bx * 128;
    // uneven split: 1000 atoms of 32 = 18*55 + 10; splits 0..9 get 56
    const int tile0 = s * 55 + min(s, 10);
    const int ntile = 55 + (s < 10 ? 1 : 0);

    // usage copy (ordered before topk's atomics by stream order)
    if (bx == 0 && s == 0)
        ((float4*)usage_out)[t] = ((const float4*)usage_in)[t];

#if HAS_TCGEN05
    // ======================= tcgen05 tf32 path =============================
    __shared__ uint32_t s_tmem;
    __shared__ __align__(8) unsigned long long s_mbar[NSTAGE];
    const int wid  = t >> 5;
    const int lane = t & 31;

    char* bp = (char*)(((uintptr_t)dynf + 1023) & ~(uintptr_t)1023);
    const uint32_t base = smem_u32(bp);
    const uint32_t tmem_ptr_addr = smem_u32(&s_tmem);
    uint32_t mb[NSTAGE];
#pragma unroll
    for (int i = 0; i < NSTAGE; i++) mb[i] = smem_u32(&s_mbar[i]);

    if (wid == 0) {
        tmem_alloc(tmem_ptr_addr, 128);
        tmem_relinquish();
    }
    if (t == 0) {
#pragma unroll
        for (int i = 0; i < NSTAGE; i++) mbar_init(mb[i], 1);
    }
    __syncthreads();
    uint32_t tmem;
    asm volatile("ld.shared.b32 %0, [%1];" : "=r"(tmem) : "r"(tmem_ptr_addr));

    const int rA = t >> 1;               // row 0..127
    const int cg = (t & 1) * 4;          // float4 group base
    const float* aRow = A  + (size_t)rA * D_SZ;
    const float* bRow = Bm + (size_t)(n0 + rA) * D_SZ;
    uint32_t stsOff[4];
#pragma unroll
    for (int j = 0; j < 4; j++)
        stsOff[j] = sw128((uint32_t)rA * 128u + (uint32_t)(cg + j) * 16u);

    float nb = 0.f, na = 0.f;

    // register double buffers for prefetch
    float4 av[2][4], bv[2][4];
    {
        const float4* a4 = (const float4*)(aRow + (size_t)tile0 * BKA);
        const float4* b4 = (const float4*)(bRow + (size_t)tile0 * BKA);
#pragma unroll
        for (int j = 0; j < 4; j++) { av[0][j] = a4[cg + j]; bv[0][j] = b4[cg + j]; }
    }

#pragma unroll 2
    for (int it = 0; it < ntile; it++) {
        const int stg = it % NSTAGE;
        const int pb  = it & 1;

        // PREFETCH tile it+1 before the wait — its latency is covered by the
        // whole split/STS/sync/MMA phase of tile it.
        if (it + 1 < ntile) {
            const int k1 = (tile0 + it + 1) * BKA;
            const float4* a4 = (const float4*)(aRow + k1);
            const float4* b4 = (const float4*)(bRow + k1);
#pragma unroll
            for (int j = 0; j < 4; j++) { av[pb ^ 1][j] = a4[cg + j]; bv[pb ^ 1][j] = b4[cg + j]; }
        }

        // wait stage free: MMA of (it - NSTAGE) done
        if (it >= NSTAGE) mbar_wait(mb[stg], ((it - NSTAGE) / NSTAGE) & 1);

        // split hi/lo + STS (+ fused norms) from the CURRENT tile's registers
        char* sb = bp + stg * STAGE_BYTES;
#pragma unroll
        for (int j = 0; j < 4; j++) {
            float4 v = av[pb][j], h, l;
            if (bx == 0) na += v.x * v.x + v.y * v.y + v.z * v.z + v.w * v.w;
            h.x = __uint_as_float(__float_as_uint(v.x) & 0xFFFFE000u); l.x = v.x - h.x;
            h.y = __uint_as_float(__float_as_uint(v.y) & 0xFFFFE000u); l.y = v.y - h.y;
            h.z = __uint_as_float(__float_as_uint(v.z) & 0xFFFFE000u); l.z = v.z - h.z;
            h.w = __uint_as_float(__float_as_uint(v.w) & 0xFFFFE000u); l.w = v.w - h.w;
            *(float4*)(sb + 0 * TILE_BYTES + stsOff[j]) = h;
            *(float4*)(sb + 1 * TILE_BYTES + stsOff[j]) = l;
            float4 w = bv[pb][j];
            nb += w.x * w.x + w.y * w.y + w.z * w.z + w.w * w.w;
            h.x = __uint_as_float(__float_as_uint(w.x) & 0xFFFFE000u); l.x = w.x - h.x;
            h.y = __uint_as_float(__float_as_uint(w.y) & 0xFFFFE000u); l.y = w.y - h.y;
            h.z = __uint_as_float(__float_as_uint(w.z) & 0xFFFFE000u); l.z = w.z - h.z;
            h.w = __uint_as_float(__float_as_uint(w.w) & 0xFFFFE000u); l.w = w.w - h.w;
            *(float4*)(sb + 2 * TILE_BYTES + stsOff[j]) = h;
            *(float4*)(sb + 3 * TILE_BYTES + stsOff[j]) = l;
        }
        __syncthreads();

        // MMA issue for this stage
        if (wid == 0 && elect1()) {
            asm volatile("fence.proxy.async.shared::cta;" ::: "memory");
            uint32_t sbu = base + stg * STAGE_BYTES;
            uint64_t dAh = smem_desc(sbu);
            uint64_t dAl = smem_desc(sbu + 1 * TILE_BYTES);
            uint64_t dBh = smem_desc(sbu + 2 * TILE_BYTES);
            uint64_t dBl = smem_desc(sbu + 3 * TILE_BYTES);
#pragma unroll
            for (int k = 0; k < 4; k++) mma_tf32_ss(tmem, dAh + 2 * k, dBh + 2 * k, (it > 0) || (k > 0));
#pragma unroll
            for (int k = 0; k < 4; k++) mma_tf32_ss(tmem, dAh + 2 * k, dBl + 2 * k, 1u);
#pragma unroll
            for (int k = 0; k < 4; k++) mma_tf32_ss(tmem, dAl + 2 * k, dBh + 2 * k, 1u);
            mma_commit(mb[stg]);
        }
    }

    // drain: tcgen05 ops complete in order -> wait for the last commit only
    mbar_wait(mb[(ntile - 1) % NSTAGE], ((ntile - 1) / NSTAGE) & 1);
    asm volatile("tcgen05.fence::after_thread_sync;" ::: "memory");

    // norm writeout: thread pair (2r,2r+1) owns row r
    nb += __shfl_xor_sync(0xFFFFFFFFu, nb, 1);
    if ((t & 1) == 0) g_cnp[s][n0 + rA] = nb;
    if (bx == 0) {
        na += __shfl_xor_sync(0xFFFFFFFFu, na, 1);
        if ((t & 1) == 0) g_lnp[s][rA] = na;
    }

    // epilogue: TMEM -> g_part.  warps 0-3: cols 0-63, warps 4-7: cols 64-127
    {
        const int colb = (wid >> 2) * 64;
        const int m = (wid & 3) * 32 + lane;
        float* dst = &g_part[s][(size_t)m * C_SZ + n0 + colb];
        uint32_t dr[32];
        LDTM_X32(dr, tmem + colb);
        asm volatile("tcgen05.wait::ld.sync.aligned;" ::: "memory");
#pragma unroll
        for (int j = 0; j < 8; j++)
            ((float4*)dst)[j] = make_float4(__uint_as_float(dr[4 * j + 0]), __uint_as_float(dr[4 * j + 1]),
                                            __uint_as_float(dr[4 * j + 2]), __uint_as_float(dr[4 * j + 3]));
        LDTM_X32(dr, tmem + colb + 32);
        asm volatile("tcgen05.wait::ld.sync.aligned;" ::: "memory");
#pragma unroll
        for (int j = 0; j < 8; j++)
            ((float4*)(dst + 32))[j] = make_float4(__uint_as_float(dr[4 * j + 0]), __uint_as_float(dr[4 * j + 1]),
                                                   __uint_as_float(dr[4 * j + 2]), __uint_as_float(dr[4 * j + 3]));
    }
    __syncthreads();
    if (wid == 0) tmem_dealloc(tmem, 128);

#else
    // ======= FFMA2 fallback (base pass; never selected at runtime) =========
    float* As = dynf;                       // 128 x PT
    float* Bs = dynf + FB_TILE_FLOATS;      // 128 x PT

    const int row  = t >> 1;
    const int half = t & 1;
    const int ty   = t >> 4;
    const int tx   = t & 15;

    const float* aSrc = A  + (size_t)row * D_SZ + half * 16;
    const float* bSrc = Bm + (size_t)(n0 + row) * D_SZ + half * 16;

    unsigned long long acc[8][8];
#pragma unroll
    for (int i = 0; i < 8; i++)
#pragma unroll
        for (int j = 0; j < 8; j++) acc[i][j] = 0ULL;

    float nb = 0.f, na = 0.f;

    for (int it = 0; it < ntile; it++) {
        const int k0 = (tile0 + it) * BKA;
        const float4* a4 = (const float4*)(aSrc + k0);
        const float4* b4 = (const float4*)(bSrc + k0);
        float4 a0 = a4[0], a1 = a4[1], a2v = a4[2], a3v = a4[3];
        float4 b0 = b4[0], b1 = b4[1], b2v = b4[2], b3v = b4[3];
        if (bx == 0) {
            na += a0.x * a0.x + a0.y * a0.y + a0.z * a0.z + a0.w * a0.w
                + a1.x * a1.x + a1.y * a1.y + a1.z * a1.z + a1.w * a1.w
                + a2v.x * a2v.x + a2v.y * a2v.y + a2v.z * a2v.z + a2v.w * a2v.w
                + a3v.x * a3v.x + a3v.y * a3v.y + a3v.z * a3v.z + a3v.w * a3v.w;
        }
        nb += b0.x * b0.x + b0.y * b0.y + b0.z * b0.z + b0.w * b0.w
            + b1.x * b1.x + b1.y * b1.y + b1.z * b1.z + b1.w * b1.w
            + b2v.x * b2v.x + b2v.y * b2v.y + b2v.z * b2v.z + b2v.w * b2v.w
            + b3v.x * b3v.x + b3v.y * b3v.y + b3v.z * b3v.z + b3v.w * b3v.w;
        float* ad = As + row * PT + half * 16;
        float* bd = Bs + row * PT + half * 16;
        *(float4*)(ad)      = a0;  *(float4*)(ad + 4)  = a1;
        *(float4*)(ad + 8)  = a2v; *(float4*)(ad + 12) = a3v;
        *(float4*)(bd)      = b0;  *(float4*)(bd + 4)  = b1;
        *(float4*)(bd + 8)  = b2v; *(float4*)(bd + 12) = b3v;
        __syncthreads();

#pragma unroll
        for (int k4 = 0; k4 < 8; k4++) {
            ulonglong2 a2[8];
#pragma unroll
            for (int i = 0; i < 8; i++)
                a2[i] = *(const ulonglong2*)(As + (ty + 16 * i) * PT + k4 * 4);
            ulonglong2 b2[8];
#pragma unroll
            for (int j = 0; j < 8; j++)
                b2[j] = *(const ulonglong2*)(Bs + (tx + 16 * j) * PT + k4 * 4);
#pragma unroll
            for (int i = 0; i < 8; i++)
#pragma unroll
                for (int j = 0; j < 8; j++) {
                    ffma2(acc[i][j], a2[i].x, b2[j].x);
                    ffma2(acc[i][j], a2[i].y, b2[j].y);
                }
        }
        __syncthreads();
    }

    nb += __shfl_xor_sync(0xFFFFFFFFu, nb, 1);
    if (half == 0) g_cnp[s][n0 + row] = nb;
    if (bx == 0) {
        na += __shfl_xor_sync(0xFFFFFFFFu, na, 1);
        if (half == 0) g_lnp[s][row] = na;
    }

    float* op = g_part[s];
#pragma unroll
    for (int i = 0; i < 8; i++) {
        const int m = ty + 16 * i;
#pragma unroll
        for (int j = 0; j < 8; j++) {
            float lo, hi;
            unpack2(acc[i][j], lo, hi);
            op[(size_t)m * C_SZ + n0 + tx + 16 * j] = lo + hi;
        }
    }
#endif
}

// ---------------------------------------------------------------------------
// Per-row: reduce partials (+ inline norm sums) -> dist, top-5 (lowest-index
// tie-break), softmax, outputs, usage scatter-add, stash for quantize.
// ---------------------------------------------------------------------------
__global__ void topk_kernel(float* __restrict__ out) {
    const int b   = blockIdx.x;
    const int tid = threadIdx.x;

    __shared__ float sd[C_SZ];
    __shared__ float rv[256];
    __shared__ int   ri[256];
    __shared__ float topd[TOPK];
    __shared__ int   topi[TOPK];
    __shared__ float s_ln;

    if (tid == 0) {
        float v = 0.f;
#pragma unroll
        for (int s = 0; s < SPLITS; s++) v += g_lnp[s][b];
        s_ln = v;
    }
    __syncthreads();
    const float ln = s_ln;

    for (int c = tid; c < C_SZ; c += 256) {
        float dot = 0.f, cn = 0.f;
#pragma unroll
        for (int s = 0; s < SPLITS; s++) {
            dot += g_part[s][b * C_SZ + c];
            cn  += g_cnp[s][c];
        }
        float d2 = ln + cn - 2.f * dot;
        sd[c] = sqrtf(fmaxf(d2, 0.f));
    }
    __syncthreads();

    for (int k = 0; k < TOPK; k++) {
        float best = FLT_MAX;
        int   bi   = C_SZ;
        for (int c = tid; c < C_SZ; c += 256) {
            float d = sd[c];
            if (d < best || (d == best && c < bi)) { best = d; bi = c; }
        }
        rv[tid] = best; ri[tid] = bi;
        __syncthreads();
        for (int s = 128; s > 0; s >>= 1) {
            if (tid < s) {
                float o = rv[tid + s]; int oi = ri[tid + s];
                if (o < rv[tid] || (o == rv[tid] && oi < ri[tid])) {
                    rv[tid] = o; ri[tid] = oi;
                }
            }
            __syncthreads();
        }
        if (tid == 0) {
            topd[k] = rv[0];
            topi[k] = ri[0];
            sd[ri[0]] = FLT_MAX;
        }
        __syncthreads();
    }

    if (tid == 0) {
        float m0 = topd[0];
        float e[TOPK], ssum = 0.f;
#pragma unroll
        for (int k = 0; k < TOPK; k++) {
            e[k] = expf(-(topd[k] - m0) / TEMP);
            ssum += e[k];
        }
        float inv = 1.f / ssum;
        out[OFF_IDX  + b] = (float)topi[0];
        out[OFF_DIST + b] = topd[0];
#pragma unroll
        for (int k = 0; k < TOPK; k++) {
            float w = e[k] * inv;
            atomicAdd(&out[OFF_USAGE + topi[k]], w);
            g_topw[b][k] = w;
            g_topi[b][k] = topi[k];
        }
    }
}

// ---------------------------------------------------------------------------
// quantized[b] = sum_k w[b][k] * codebook[idx[b][k]]   grid (B, 16 chunks)
// ---------------------------------------------------------------------------
__global__ void quant_kernel(const float* __restrict__ codebook,
                             float* __restrict__ out) {
    const int b     = blockIdx.x;
    const int chunk = blockIdx.y;
    const int tid   = threadIdx.x;
    __shared__ int   si[TOPK];
    __shared__ float sw[TOPK];
    if (tid < TOPK) { si[tid] = g_topi[b][tid]; sw[tid] = g_topw[b][tid]; }
    __syncthreads();

    const float4* cb = (const float4*)codebook;
    float4* outq = (float4*)(out + OFF_Q) + (size_t)b * D4;

    const float4* r0 = cb + (size_t)si[0] * D4;
    const float4* r1 = cb + (size_t)si[1] * D4;
    const float4* r2 = cb + (size_t)si[2] * D4;
    const float4* r3 = cb + (size_t)si[3] * D4;
    const float4* r4 = cb + (size_t)si[4] * D4;
    const float w0 = sw[0], w1 = sw[1], w2 = sw[2], w3 = sw[3], w4 = sw[4];

    const int p0 = chunk * (D4 / 16);
    const int p1 = p0 + (D4 / 16);
    for (int p = p0 + tid; p < p1; p += 256) {
        float4 v0 = r0[p], v1 = r1[p], v2 = r2[p], v3 = r3[p], v4 = r4[p];
        float4 r;
        r.x = w0 * v0.x + w1 * v1.x + w2 * v2.x + w3 * v3.x + w4 * v4.x;
        r.y = w0 * v0.y + w1 * v1.y + w2 * v2.y + w3 * v3.y + w4 * v4.y;
        r.z = w0 * v0.z + w1 * v1.z + w2 * v2.z + w3 * v3.z + w4 * v4.z;
        r.w = w0 * v0.w + w1 * v1.w + w2 * v2.w + w3 * v3.w + w4 * v4.w;
        outq[p] = r;
    }
}

// ---------------------------------------------------------------------------
extern "C" void kernel_launch(void* const* d_in, const int* in_sizes, int n_in,
                              void* d_out, int out_size) {
    const float* latent   = (const float*)d_in[0];
    const float* codebook = (const float*)d_in[1];
    const float* usage    = (const float*)d_in[2];
    float* out = (float*)d_out;

    cudaFuncSetAttribute((const void*)gemm_kernel,
                         cudaFuncAttributeMaxDynamicSharedMemorySize, DYN_SMEM);
    gemm_kernel<<<dim3(NB, SPLITS), 256, DYN_SMEM>>>(latent, codebook,
                                                     usage, out + OFF_USAGE);
    topk_kernel<<<B_SZ, 256>>>(out);
    quant_kernel<<<dim3(B_SZ, 16), 256>>>(codebook, out);
}

// round 16
// speedup vs baseline: 1.4108x; 1.0454x over previous
#include <cuda_runtime.h>
#include <cstdint>
#include <math.h>
#include <float.h>

// Problem constants
#define B_SZ 128
#define C_SZ 1024
#define D_SZ 32000           // 8*250*16
#define D4   (D_SZ/4)
#define TOPK 5
#define TEMP 0.1f

// GEMM structure: K atoms of 32 floats (128B rows, SW128), split-K, N-tile 256
#define BKA    32
#define SPLITS 36             // 4 * 36 = 144 CTAs = 1 wave
#define NB     4              // N tiles of 256

// tensor path smem per stage: Ah|Al (128x128B each) + Bh|Bl (256x128B each)
#define ATILE_BYTES 16384
#define BTILE_BYTES 32768
#define STAGE_BYTES (2 * ATILE_BYTES + 2 * BTILE_BYTES)   // 98304
#define NSTAGE 2
#define DYN_SMEM (NSTAGE * STAGE_BYTES + 1024)            // 197632

// stage-internal offsets
#define OFF_AH 0
#define OFF_AL ATILE_BYTES
#define OFF_BH (2 * ATILE_BYTES)
#define OFF_BL (2 * ATILE_BYTES + BTILE_BYTES)

// idesc tf32 N=256: dtype=F32(1)<<4, atype=TF32(2)<<7, btype=TF32(2)<<10,
// N/8(32)<<17, M/16(8)<<24
#define MMA_IDESC 0x8400910u

// Output layout (float32): quantized | main_indices | main_distances | usage_new
#define OFF_Q     0
#define OFF_IDX   (B_SZ * D_SZ)
#define OFF_DIST  (OFF_IDX + B_SZ)
#define OFF_USAGE (OFF_DIST + B_SZ)

// Scratch (device globals — no allocation allowed)
__device__ float g_part[SPLITS][B_SZ * C_SZ];   // split-K partial dots
__device__ float g_cnp[SPLITS][C_SZ];           // codebook norm partials
__device__ float g_lnp[SPLITS][B_SZ];           // latent norm partials
__device__ float g_topw[B_SZ][8];
__device__ int   g_topi[B_SZ][8];

// Feature gate: tcgen05 exists only in the sm_103a compilation pass.
#if defined(__CUDA_ARCH__) && defined(__CUDA_ARCH_FEAT_SM103_ALL)
#define HAS_TCGEN05 1
#else
#define HAS_TCGEN05 0
#endif

// ---------------------------------------------------------------------------
// Common helpers
// ---------------------------------------------------------------------------
__device__ __forceinline__ uint32_t smem_u32(const void* p) {
    uint32_t a;
    asm("{ .reg .u64 t; cvta.to.shared.u64 t, %1; cvt.u32.u64 %0, t; }" : "=r"(a) : "l"(p));
    return a;
}

#if HAS_TCGEN05
// ---------------------------------------------------------------------------
// tcgen05 / mbarrier helpers (sm_103a pass only)
// ---------------------------------------------------------------------------
__device__ __forceinline__ bool elect1() {
    uint32_t p;
    asm volatile("{ .reg .pred p; elect.sync _|p, 0xFFFFFFFF; selp.b32 %0, 1, 0, p; }" : "=r"(p));
    return p != 0;
}
__device__ __forceinline__ void mbar_init(uint32_t mbar, uint32_t cnt) {
    asm volatile("mbarrier.init.shared.b64 [%0], %1;" :: "r"(mbar), "r"(cnt) : "memory");
}
__device__ __forceinline__ void mbar_wait(uint32_t mbar, uint32_t parity) {
    asm volatile("{\n\t.reg .pred P;\n\t"
                 "WL_%=:\n\t"
                 "mbarrier.try_wait.parity.acquire.cta.shared::cta.b64 P, [%0], %1, 0x989680;\n\t"
                 "@P bra.uni WD_%=;\n\t"
                 "bra.uni WL_%=;\n\t"
                 "WD_%=:\n\t}"
                 :: "r"(mbar), "r"(parity) : "memory");
}
__device__ __forceinline__ void tmem_alloc(uint32_t dst_smem, uint32_t ncols) {
    asm volatile("tcgen05.alloc.cta_group::1.sync.aligned.shared::cta.b32 [%0], %1;"
                 :: "r"(dst_smem), "r"(ncols) : "memory");
}
__device__ __forceinline__ void tmem_relinquish() {
    asm volatile("tcgen05.relinquish_alloc_permit.cta_group::1.sync.aligned;");
}
__device__ __forceinline__ void tmem_dealloc(uint32_t tmem, uint32_t ncols) {
    asm volatile("tcgen05.dealloc.cta_group::1.sync.aligned.b32 %0, %1;" :: "r"(tmem), "r"(ncols));
}
__device__ __forceinline__ void mma_commit(uint32_t mbar) {
    asm volatile("tcgen05.commit.cta_group::1.mbarrier::arrive::one.shared::cluster.b64 [%0];"
                 :: "r"(mbar) : "memory");
}
__device__ __forceinline__ void mma_tf32_ss(uint32_t d, uint64_t ad, uint64_t bd, uint32_t en) {
    asm volatile("{\n\t.reg .pred p;\n\tsetp.ne.u32 p, %4, 0;\n\t"
                 "tcgen05.mma.cta_group::1.kind::tf32 [%0], %1, %2, %3, {%5, %5, %5, %5}, p;\n\t}"
                 :: "r"(d), "l"(ad), "l"(bd), "r"(MMA_IDESC), "r"(en), "r"(0u)
                 : "memory");
}
// SW128 K-major descriptor: layout=2(SW128), version=1, SBO=64, LBO=1
__device__ __forceinline__ uint64_t smem_desc(uint32_t addr) {
    return ((uint64_t)2 << 61) | ((uint64_t)1 << 46) | ((uint64_t)64 << 32) |
           ((uint64_t)1 << 16) | ((uint64_t)(addr >> 4) & 0x3FFF);
}
__device__ __forceinline__ uint32_t sw128(uint32_t off) { return off ^ ((off >> 3) & 0x70u); }

#define LDTM_X32(r, addr)                                                          \
    asm volatile("tcgen05.ld.sync.aligned.32x32b.x32.b32 "                         \
        "{%0, %1, %2, %3, %4, %5, %6, %7, %8, %9, %10, %11, %12, %13, %14, %15, "  \
        " %16, %17, %18, %19, %20, %21, %22, %23, %24, %25, %26, %27, %28, %29, %30, %31}, [%32];" \
        : "=r"((r)[0]), "=r"((r)[1]), "=r"((r)[2]), "=r"((r)[3]),                  \
          "=r"((r)[4]), "=r"((r)[5]), "=r"((r)[6]), "=r"((r)[7]),                  \
          "=r"((r)[8]), "=r"((r)[9]), "=r"((r)[10]), "=r"((r)[11]),                \
          "=r"((r)[12]), "=r"((r)[13]), "=r"((r)[14]), "=r"((r)[15]),              \
          "=r"((r)[16]), "=r"((r)[17]), "=r"((r)[18]), "=r"((r)[19]),              \
          "=r"((r)[20]), "=r"((r)[21]), "=r"((r)[22]), "=r"((r)[23]),              \
          "=r"((r)[24]), "=r"((r)[25]), "=r"((r)[26]), "=r"((r)[27]),              \
          "=r"((r)[28]), "=r"((r)[29]), "=r"((r)[30]), "=r"((r)[31])               \
        : "r"(addr))
#endif // HAS_TCGEN05

// ---------------------------------------------------------------------------
// GEMM: grid (NB, SPLITS), 256 threads. N-tile = 256.
// sm_103a pass: tcgen05 tf32 (3xTF32), SW128 tiles, NSTAGE=2 ring,
//   register double-buffer prefetch (R15 structure, amortized over N=256).
// base pass (never selected at runtime): slow-but-correct FFMA fallback.
// ---------------------------------------------------------------------------
__global__ __launch_bounds__(256, 1)
void gemm_kernel(const float* __restrict__ A,   // latent  [128][32000]
                 const float* __restrict__ Bm,  // codebook[1024][32000]
                 const float* __restrict__ usage_in,
                 float* __restrict__ usage_out)
{
    extern __shared__ float dynf[];
    const int t  = threadIdx.x;
    const int bx = blockIdx.x;
    const int s  = blockIdx.y;
    const int n0 = bx * 256;
    // uneven split: 1000 atoms of 32 = 36*27 + 28; splits 0..27 get 28
    const int tile0 = s * 27 + min(s, 28);
    const int ntile = 27 + (s < 28 ? 1 : 0);

    // usage copy (ordered before topk's atomics by stream order)
    if (bx == 0 && s == 0)
        ((float4*)usage_out)[t] = ((const float4*)usage_in)[t];

#if HAS_TCGEN05
    // ======================= tcgen05 tf32 path =============================
    __shared__ uint32_t s_tmem;
    __shared__ __align__(8) unsigned long long s_mbar[NSTAGE];
    const int wid  = t >> 5;
    const int lane = t & 31;

    char* bp = (char*)(((uintptr_t)dynf + 1023) & ~(uintptr_t)1023);
    const uint32_t base = smem_u32(bp);
    const uint32_t tmem_ptr_addr = smem_u32(&s_tmem);
    uint32_t mb[NSTAGE];
#pragma unroll
    for (int i = 0; i < NSTAGE; i++) mb[i] = smem_u32(&s_mbar[i]);

    if (wid == 0) {
        tmem_alloc(tmem_ptr_addr, 256);
        tmem_relinquish();
    }
    if (t == 0) {
#pragma unroll
        for (int i = 0; i < NSTAGE; i++) mbar_init(mb[i], 1);
    }
    __syncthreads();
    uint32_t tmem;
    asm volatile("ld.shared.b32 %0, [%1];" : "=r"(tmem) : "r"(tmem_ptr_addr));

    const int rA = t >> 1;               // A row 0..127 (2 threads per row)
    const int cg = (t & 1) * 4;          // A float4 group base
    const int rB = t;                    // B row 0..255 (1 thread per row)
    const float* aRow = A  + (size_t)rA * D_SZ;
    const float* bRow = Bm + (size_t)(n0 + rB) * D_SZ;
    uint32_t stsA[4], stsB[8];
#pragma unroll
    for (int j = 0; j < 4; j++)
        stsA[j] = sw128((uint32_t)rA * 128u + (uint32_t)(cg + j) * 16u);
#pragma unroll
    for (int q = 0; q < 8; q++)
        stsB[q] = sw128((uint32_t)rB * 128u + (uint32_t)q * 16u);

    float nb = 0.f, na = 0.f;

    // register double buffers for prefetch
    float4 av[2][4], bv[2][8];
    {
        const float4* a4 = (const float4*)(aRow + (size_t)tile0 * BKA);
        const float4* b4 = (const float4*)(bRow + (size_t)tile0 * BKA);
#pragma unroll
        for (int j = 0; j < 4; j++) av[0][j] = a4[cg + j];
#pragma unroll
        for (int q = 0; q < 8; q++) bv[0][q] = b4[q];
    }

#pragma unroll 2
    for (int it = 0; it < ntile; it++) {
        const int stg = it & 1;
        const int pb  = it & 1;

        // PREFETCH tile it+1 before the wait
        if (it + 1 < ntile) {
            const int k1 = (tile0 + it + 1) * BKA;
            const float4* a4 = (const float4*)(aRow + k1);
            const float4* b4 = (const float4*)(bRow + k1);
#pragma unroll
            for (int j = 0; j < 4; j++) av[pb ^ 1][j] = a4[cg + j];
#pragma unroll
            for (int q = 0; q < 8; q++) bv[pb ^ 1][q] = b4[q];
        }

        // wait stage free: MMA of (it - NSTAGE) done
        if (it >= NSTAGE) mbar_wait(mb[stg], ((it - NSTAGE) / NSTAGE) & 1);

        // split hi/lo + STS (+ fused norms) from CURRENT tile registers
        char* sb = bp + stg * STAGE_BYTES;
#pragma unroll
        for (int j = 0; j < 4; j++) {
            float4 v = av[pb][j], h, l;
            if (bx == 0) na += v.x * v.x + v.y * v.y + v.z * v.z + v.w * v.w;
            h.x = __uint_as_float(__float_as_uint(v.x) & 0xFFFFE000u); l.x = v.x - h.x;
            h.y = __uint_as_float(__float_as_uint(v.y) & 0xFFFFE000u); l.y = v.y - h.y;
            h.z = __uint_as_float(__float_as_uint(v.z) & 0xFFFFE000u); l.z = v.z - h.z;
            h.w = __uint_as_float(__float_as_uint(v.w) & 0xFFFFE000u); l.w = v.w - h.w;
            *(float4*)(sb + OFF_AH + stsA[j]) = h;
            *(float4*)(sb + OFF_AL + stsA[j]) = l;
        }
#pragma unroll
        for (int q = 0; q < 8; q++) {
            float4 w = bv[pb][q], h, l;
            nb += w.x * w.x + w.y * w.y + w.z * w.z + w.w * w.w;
            h.x = __uint_as_float(__float_as_uint(w.x) & 0xFFFFE000u); l.x = w.x - h.x;
            h.y = __uint_as_float(__float_as_uint(w.y) & 0xFFFFE000u); l.y = w.y - h.y;
            h.z = __uint_as_float(__float_as_uint(w.z) & 0xFFFFE000u); l.z = w.z - h.z;
            h.w = __uint_as_float(__float_as_uint(w.w) & 0xFFFFE000u); l.w = w.w - h.w;
            *(float4*)(sb + OFF_BH + stsB[q]) = h;
            *(float4*)(sb + OFF_BL + stsB[q]) = l;
        }
        __syncthreads();

        // MMA issue for this stage: N=256, 4 K-steps x 3 terms
        if (wid == 0 && elect1()) {
            asm volatile("fence.proxy.async.shared::cta;" ::: "memory");
            uint32_t sbu = base + stg * STAGE_BYTES;
            uint64_t dAh = smem_desc(sbu + OFF_AH);
            uint64_t dAl = smem_desc(sbu + OFF_AL);
            uint64_t dBh = smem_desc(sbu + OFF_BH);
            uint64_t dBl = smem_desc(sbu + OFF_BL);
#pragma unroll
            for (int k = 0; k < 4; k++) mma_tf32_ss(tmem, dAh + 2 * k, dBh + 2 * k, (it > 0) || (k > 0));
#pragma unroll
            for (int k = 0; k < 4; k++) mma_tf32_ss(tmem, dAh + 2 * k, dBl + 2 * k, 1u);
#pragma unroll
            for (int k = 0; k < 4; k++) mma_tf32_ss(tmem, dAl + 2 * k, dBh + 2 * k, 1u);
            mma_commit(mb[stg]);
        }
    }

    // drain: tcgen05 ops complete in order -> wait for the last commit only
    mbar_wait(mb[(ntile - 1) & 1], ((ntile - 1) / NSTAGE) & 1);
    asm volatile("tcgen05.fence::after_thread_sync;" ::: "memory");

    // norm writeout
    nb += 0.f;
    g_cnp[s][n0 + rB] = nb;               // one thread per codebook row
    if (bx == 0) {
        float v = na + __shfl_xor_sync(0xFFFFFFFFu, na, 1);
        if ((t & 1) == 0) g_lnp[s][rA] = v;
    }

    // epilogue: TMEM D (128x256) -> g_part.
    // warp w: rows (w&3)*32+lane, cols (w>>2)*128 .. +127
    {
        const int colb = (wid >> 2) * 128;
        const int m = (wid & 3) * 32 + lane;
        float* dst = &g_part[s][(size_t)m * C_SZ + n0 + colb];
        uint32_t dr[32];
#pragma unroll
        for (int blk = 0; blk < 4; blk++) {
            LDTM_X32(dr, tmem + colb + blk * 32);
            asm volatile("tcgen05.wait::ld.sync.aligned;" ::: "memory");
#pragma unroll
            for (int j = 0; j < 8; j++)
                ((float4*)(dst + blk * 32))[j] =
                    make_float4(__uint_as_float(dr[4 * j + 0]), __uint_as_float(dr[4 * j + 1]),
                                __uint_as_float(dr[4 * j + 2]), __uint_as_float(dr[4 * j + 3]));
        }
    }
    __syncthreads();
    if (wid == 0) tmem_dealloc(tmem, 256);

#else
    // ===== FFMA fallback (base pass; never selected at runtime; correct) ===
    // Each thread owns codebook row n0+t; accumulate over this split's k-range.
    const int rB = t;
    const float* bRow = Bm + (size_t)(n0 + rB) * D_SZ;
    const int klo = tile0 * BKA;
    const int khi = (tile0 + ntile) * BKA;

    float nb = 0.f;
    for (int k = klo; k < khi; k += 4) {
        float4 w = *(const float4*)(bRow + k);
        nb += w.x * w.x + w.y * w.y + w.z * w.z + w.w * w.w;
    }
    g_cnp[s][n0 + rB] = nb;

    if (bx == 0 && t < B_SZ) {
        const float* aRow = A + (size_t)t * D_SZ;
        float na = 0.f;
        for (int k = klo; k < khi; k += 4) {
            float4 v = *(const float4*)(aRow + k);
            na += v.x * v.x + v.y * v.y + v.z * v.z + v.w * v.w;
        }
        g_lnp[s][t] = na;
    }

    for (int m = 0; m < B_SZ; m++) {
        const float* aRow = A + (size_t)m * D_SZ;
        float acc = 0.f;
        for (int k = klo; k < khi; k += 4) {
            float4 v = *(const float4*)(aRow + k);
            float4 w = *(const float4*)(bRow + k);
            acc += v.x * w.x + v.y * w.y + v.z * w.z + v.w * w.w;
        }
        g_part[s][(size_t)m * C_SZ + n0 + rB] = acc;
    }
#endif
}

// ---------------------------------------------------------------------------
// Per-row: reduce partials (+ inline norm sums) -> dist, top-5 (lowest-index
// tie-break), softmax, outputs, usage scatter-add, stash for quantize.
// ---------------------------------------------------------------------------
__global__ void topk_kernel(float* __restrict__ out) {
    const int b   = blockIdx.x;
    const int tid = threadIdx.x;

    __shared__ float sd[C_SZ];
    __shared__ float rv[256];
    __shared__ int   ri[256];
    __shared__ float topd[TOPK];
    __shared__ int   topi[TOPK];
    __shared__ float s_ln;

    if (tid == 0) {
        float v = 0.f;
#pragma unroll
        for (int s = 0; s < SPLITS; s++) v += g_lnp[s][b];
        s_ln = v;
    }
    __syncthreads();
    const float ln = s_ln;

    for (int c = tid; c < C_SZ; c += 256) {
        float dot = 0.f, cn = 0.f;
#pragma unroll
        for (int s = 0; s < SPLITS; s++) {
            dot += g_part[s][b * C_SZ + c];
            cn  += g_cnp[s][c];
        }
        float d2 = ln + cn - 2.f * dot;
        sd[c] = sqrtf(fmaxf(d2, 0.f));
    }
    __syncthreads();

    for (int k = 0; k < TOPK; k++) {
        float best = FLT_MAX;
        int   bi   = C_SZ;
        for (int c = tid; c < C_SZ; c += 256) {
            float d = sd[c];
            if (d < best || (d == best && c < bi)) { best = d; bi = c; }
        }
        rv[tid] = best; ri[tid] = bi;
        __syncthreads();
        for (int s = 128; s > 0; s >>= 1) {
            if (tid < s) {
                float o = rv[tid + s]; int oi = ri[tid + s];
                if (o < rv[tid] || (o == rv[tid] && oi < ri[tid])) {
                    rv[tid] = o; ri[tid] = oi;
                }
            }
            __syncthreads();
        }
        if (tid == 0) {
            topd[k] = rv[0];
            topi[k] = ri[0];
            sd[ri[0]] = FLT_MAX;
        }
        __syncthreads();
    }

    if (tid == 0) {
        float m0 = topd[0];
        float e[TOPK], ssum = 0.f;
#pragma unroll
        for (int k = 0; k < TOPK; k++) {
            e[k] = expf(-(topd[k] - m0) / TEMP);
            ssum += e[k];
        }
        float inv = 1.f / ssum;
        out[OFF_IDX  + b] = (float)topi[0];
        out[OFF_DIST + b] = topd[0];
#pragma unroll
        for (int k = 0; k < TOPK; k++) {
            float w = e[k] * inv;
            atomicAdd(&out[OFF_USAGE + topi[k]], w);
            g_topw[b][k] = w;
            g_topi[b][k] = topi[k];
        }
    }
}

// ---------------------------------------------------------------------------
// quantized[b] = sum_k w[b][k] * codebook[idx[b][k]]   grid (B, 16 chunks)
// ---------------------------------------------------------------------------
__global__ void quant_kernel(const float* __restrict__ codebook,
                             float* __restrict__ out) {
    const int b     = blockIdx.x;
    const int chunk = blockIdx.y;
    const int tid   = threadIdx.x;
    __shared__ int   si[TOPK];
    __shared__ float sw[TOPK];
    if (tid < TOPK) { si[tid] = g_topi[b][tid]; sw[tid] = g_topw[b][tid]; }
    __syncthreads();

    const float4* cb = (const float4*)codebook;
    float4* outq = (float4*)(out + OFF_Q) + (size_t)b * D4;

    const float4* r0 = cb + (size_t)si[0] * D4;
    const float4* r1 = cb + (size_t)si[1] * D4;
    const float4* r2 = cb + (size_t)si[2] * D4;
    const float4* r3 = cb + (size_t)si[3] * D4;
    const float4* r4 = cb + (size_t)si[4] * D4;
    const float w0 = sw[0], w1 = sw[1], w2 = sw[2], w3 = sw[3], w4 = sw[4];

    const int p0 = chunk * (D4 / 16);
    const int p1 = p0 + (D4 / 16);
    for (int p = p0 + tid; p < p1; p += 256) {
        float4 v0 = r0[p], v1 = r1[p], v2 = r2[p], v3 = r3[p], v4 = r4[p];
        float4 r;
        r.x = w0 * v0.x + w1 * v1.x + w2 * v2.x + w3 * v3.x + w4 * v4.x;
        r.y = w0 * v0.y + w1 * v1.y + w2 * v2.y + w3 * v3.y + w4 * v4.y;
        r.z = w0 * v0.z + w1 * v1.z + w2 * v2.z + w3 * v3.z + w4 * v4.z;
        r.w = w0 * v0.w + w1 * v1.w + w2 * v2.w + w3 * v3.w + w4 * v4.w;
        outq[p] = r;
    }
}

// ---------------------------------------------------------------------------
extern "C" void kernel_launch(void* const* d_in, const int* in_sizes, int n_in,
                              void* d_out, int out_size) {
    const float* latent   = (const float*)d_in[0];
    const float* codebook = (const float*)d_in[1];
    const float* usage    = (const float*)d_in[2];
    float* out = (float*)d_out;

    cudaFuncSetAttribute((const void*)gemm_kernel,
                         cudaFuncAttributeMaxDynamicSharedMemorySize, DYN_SMEM);
    gemm_kernel<<<dim3(NB, SPLITS), 256, DYN_SMEM>>>(latent, codebook,
                                                     usage, out + OFF_USAGE);
    topk_kernel<<<B_SZ, 256>>>(out);
    quant_kernel<<<dim3(B_SZ, 16), 256>>>(codebook, out);
}

// round 17
// speedup vs baseline: 1.4699x; 1.0420x over previous
#include <cuda_runtime.h>
#include <cstdint>
#include <math.h>
#include <float.h>

// Problem constants
#define B_SZ 128
#define C_SZ 1024
#define D_SZ 32000           // 8*250*16
#define D4   (D_SZ/4)
#define TOPK 5
#define TEMP 0.1f

// GEMM structure: K atoms of 32 floats (128B rows, SW128), split-K, N-tile 256
#define BKA    32
#define SPLITS 36             // 4 * 36 = 144 CTAs = 1 wave
#define NB     4              // N tiles of 256

// tensor path smem per stage: Ah|Al (128x128B each) + Bh|Bl (256x128B each)
#define ATILE_BYTES 16384
#define BTILE_BYTES 32768
#define STAGE_BYTES (2 * ATILE_BYTES + 2 * BTILE_BYTES)   // 98304
#define NSTAGE 2
#define DYN_SMEM (NSTAGE * STAGE_BYTES + 1024)            // 197632

// stage-internal offsets
#define OFF_AH 0
#define OFF_AL ATILE_BYTES
#define OFF_BH (2 * ATILE_BYTES)
#define OFF_BL (2 * ATILE_BYTES + BTILE_BYTES)

// idesc tf32 N=256: dtype=F32(1)<<4, atype=TF32(2)<<7, btype=TF32(2)<<10,
// N/8(32)<<17, M/16(8)<<24
#define MMA_IDESC 0x8400910u

// Output layout (float32): quantized | main_indices | main_distances | usage_new
#define OFF_Q     0
#define OFF_IDX   (B_SZ * D_SZ)
#define OFF_DIST  (OFF_IDX + B_SZ)
#define OFF_USAGE (OFF_DIST + B_SZ)

// Scratch (device globals — no allocation allowed)
__device__ float g_part[SPLITS][B_SZ * C_SZ];   // split-K partial dots
__device__ float g_cnp[SPLITS][C_SZ];           // codebook norm partials
__device__ float g_lnp[SPLITS][B_SZ];           // latent norm partials
__device__ float g_dot[B_SZ * C_SZ];            // reduced dots
__device__ float g_cnorm[C_SZ];
__device__ float g_lnorm[B_SZ];
__device__ float g_topw[B_SZ][8];
__device__ int   g_topi[B_SZ][8];

// Feature gate: tcgen05 exists only in the sm_103a compilation pass.
#if defined(__CUDA_ARCH__) && defined(__CUDA_ARCH_FEAT_SM103_ALL)
#define HAS_TCGEN05 1
#else
#define HAS_TCGEN05 0
#endif

// ---------------------------------------------------------------------------
// Common helpers
// ---------------------------------------------------------------------------
__device__ __forceinline__ uint32_t smem_u32(const void* p) {
    uint32_t a;
    asm("{ .reg .u64 t; cvta.to.shared.u64 t, %1; cvt.u32.u64 %0, t; }" : "=r"(a) : "l"(p));
    return a;
}

#if HAS_TCGEN05
// ---------------------------------------------------------------------------
// tcgen05 / mbarrier helpers (sm_103a pass only)
// ---------------------------------------------------------------------------
__device__ __forceinline__ bool elect1() {
    uint32_t p;
    asm volatile("{ .reg .pred p; elect.sync _|p, 0xFFFFFFFF; selp.b32 %0, 1, 0, p; }" : "=r"(p));
    return p != 0;
}
__device__ __forceinline__ void mbar_init(uint32_t mbar, uint32_t cnt) {
    asm volatile("mbarrier.init.shared.b64 [%0], %1;" :: "r"(mbar), "r"(cnt) : "memory");
}
__device__ __forceinline__ void mbar_wait(uint32_t mbar, uint32_t parity) {
    asm volatile("{\n\t.reg .pred P;\n\t"
                 "WL_%=:\n\t"
                 "mbarrier.try_wait.parity.acquire.cta.shared::cta.b64 P, [%0], %1, 0x989680;\n\t"
                 "@P bra.uni WD_%=;\n\t"
                 "bra.uni WL_%=;\n\t"
                 "WD_%=:\n\t}"
                 :: "r"(mbar), "r"(parity) : "memory");
}
__device__ __forceinline__ void tmem_alloc(uint32_t dst_smem, uint32_t ncols) {
    asm volatile("tcgen05.alloc.cta_group::1.sync.aligned.shared::cta.b32 [%0], %1;"
                 :: "r"(dst_smem), "r"(ncols) : "memory");
}
__device__ __forceinline__ void tmem_relinquish() {
    asm volatile("tcgen05.relinquish_alloc_permit.cta_group::1.sync.aligned;");
}
__device__ __forceinline__ void tmem_dealloc(uint32_t tmem, uint32_t ncols) {
    asm volatile("tcgen05.dealloc.cta_group::1.sync.aligned.b32 %0, %1;" :: "r"(tmem), "r"(ncols));
}
__device__ __forceinline__ void mma_commit(uint32_t mbar) {
    asm volatile("tcgen05.commit.cta_group::1.mbarrier::arrive::one.shared::cluster.b64 [%0];"
                 :: "r"(mbar) : "memory");
}
__device__ __forceinline__ void mma_tf32_ss(uint32_t d, uint64_t ad, uint64_t bd, uint32_t en) {
    asm volatile("{\n\t.reg .pred p;\n\tsetp.ne.u32 p, %4, 0;\n\t"
                 "tcgen05.mma.cta_group::1.kind::tf32 [%0], %1, %2, %3, {%5, %5, %5, %5}, p;\n\t}"
                 :: "r"(d), "l"(ad), "l"(bd), "r"(MMA_IDESC), "r"(en), "r"(0u)
                 : "memory");
}
// SW128 K-major descriptor: layout=2(SW128), version=1, SBO=64, LBO=1
__device__ __forceinline__ uint64_t smem_desc(uint32_t addr) {
    return ((uint64_t)2 << 61) | ((uint64_t)1 << 46) | ((uint64_t)64 << 32) |
           ((uint64_t)1 << 16) | ((uint64_t)(addr >> 4) & 0x3FFF);
}
__device__ __forceinline__ uint32_t sw128(uint32_t off) { return off ^ ((off >> 3) & 0x70u); }

#define LDTM_X32(r, addr)                                                          \
    asm volatile("tcgen05.ld.sync.aligned.32x32b.x32.b32 "                         \
        "{%0, %1, %2, %3, %4, %5, %6, %7, %8, %9, %10, %11, %12, %13, %14, %15, "  \
        " %16, %17, %18, %19, %20, %21, %22, %23, %24, %25, %26, %27, %28, %29, %30, %31}, [%32];" \
        : "=r"((r)[0]), "=r"((r)[1]), "=r"((r)[2]), "=r"((r)[3]),                  \
          "=r"((r)[4]), "=r"((r)[5]), "=r"((r)[6]), "=r"((r)[7]),                  \
          "=r"((r)[8]), "=r"((r)[9]), "=r"((r)[10]), "=r"((r)[11]),                \
          "=r"((r)[12]), "=r"((r)[13]), "=r"((r)[14]), "=r"((r)[15]),              \
          "=r"((r)[16]), "=r"((r)[17]), "=r"((r)[18]), "=r"((r)[19]),              \
          "=r"((r)[20]), "=r"((r)[21]), "=r"((r)[22]), "=r"((r)[23]),              \
          "=r"((r)[24]), "=r"((r)[25]), "=r"((r)[26]), "=r"((r)[27]),              \
          "=r"((r)[28]), "=r"((r)[29]), "=r"((r)[30]), "=r"((r)[31])               \
        : "r"(addr))
#endif // HAS_TCGEN05

// ---------------------------------------------------------------------------
// GEMM: grid (NB, SPLITS), 256 threads. N-tile = 256.  (R16 — unchanged)
// ---------------------------------------------------------------------------
__global__ __launch_bounds__(256, 1)
void gemm_kernel(const float* __restrict__ A,   // latent  [128][32000]
                 const float* __restrict__ Bm,  // codebook[1024][32000]
                 const float* __restrict__ usage_in,
                 float* __restrict__ usage_out)
{
    extern __shared__ float dynf[];
    const int t  = threadIdx.x;
    const int bx = blockIdx.x;
    const int s  = blockIdx.y;
    const int n0 = bx * 256;
    // uneven split: 1000 atoms of 32 = 36*27 + 28; splits 0..27 get 28
    const int tile0 = s * 27 + min(s, 28);
    const int ntile = 27 + (s < 28 ? 1 : 0);

    // usage copy (ordered before topk's atomics by stream order)
    if (bx == 0 && s == 0)
        ((float4*)usage_out)[t] = ((const float4*)usage_in)[t];

#if HAS_TCGEN05
    // ======================= tcgen05 tf32 path =============================
    __shared__ uint32_t s_tmem;
    __shared__ __align__(8) unsigned long long s_mbar[NSTAGE];
    const int wid  = t >> 5;
    const int lane = t & 31;

    char* bp = (char*)(((uintptr_t)dynf + 1023) & ~(uintptr_t)1023);
    const uint32_t base = smem_u32(bp);
    const uint32_t tmem_ptr_addr = smem_u32(&s_tmem);
    uint32_t mb[NSTAGE];
#pragma unroll
    for (int i = 0; i < NSTAGE; i++) mb[i] = smem_u32(&s_mbar[i]);

    if (wid == 0) {
        tmem_alloc(tmem_ptr_addr, 256);
        tmem_relinquish();
    }
    if (t == 0) {
#pragma unroll
        for (int i = 0; i < NSTAGE; i++) mbar_init(mb[i], 1);
    }
    __syncthreads();
    uint32_t tmem;
    asm volatile("ld.shared.b32 %0, [%1];" : "=r"(tmem) : "r"(tmem_ptr_addr));

    const int rA = t >> 1;               // A row 0..127 (2 threads per row)
    const int cg = (t & 1) * 4;          // A float4 group base
    const int rB = t;                    // B row 0..255 (1 thread per row)
    const float* aRow = A  + (size_t)rA * D_SZ;
    const float* bRow = Bm + (size_t)(n0 + rB) * D_SZ;
    uint32_t stsA[4], stsB[8];
#pragma unroll
    for (int j = 0; j < 4; j++)
        stsA[j] = sw128((uint32_t)rA * 128u + (uint32_t)(cg + j) * 16u);
#pragma unroll
    for (int q = 0; q < 8; q++)
        stsB[q] = sw128((uint32_t)rB * 128u + (uint32_t)q * 16u);

    float nb = 0.f, na = 0.f;

    // register double buffers for prefetch
    float4 av[2][4], bv[2][8];
    {
        const float4* a4 = (const float4*)(aRow + (size_t)tile0 * BKA);
        const float4* b4 = (const float4*)(bRow + (size_t)tile0 * BKA);
#pragma unroll
        for (int j = 0; j < 4; j++) av[0][j] = a4[cg + j];
#pragma unroll
        for (int q = 0; q < 8; q++) bv[0][q] = b4[q];
    }

#pragma unroll 2
    for (int it = 0; it < ntile; it++) {
        const int stg = it & 1;
        const int pb  = it & 1;

        // PREFETCH tile it+1 before the wait
        if (it + 1 < ntile) {
            const int k1 = (tile0 + it + 1) * BKA;
            const float4* a4 = (const float4*)(aRow + k1);
            const float4* b4 = (const float4*)(bRow + k1);
#pragma unroll
            for (int j = 0; j < 4; j++) av[pb ^ 1][j] = a4[cg + j];
#pragma unroll
            for (int q = 0; q < 8; q++) bv[pb ^ 1][q] = b4[q];
        }

        // wait stage free: MMA of (it - NSTAGE) done
        if (it >= NSTAGE) mbar_wait(mb[stg], ((it - NSTAGE) / NSTAGE) & 1);

        // split hi/lo + STS (+ fused norms) from CURRENT tile registers
        char* sb = bp + stg * STAGE_BYTES;
#pragma unroll
        for (int j = 0; j < 4; j++) {
            float4 v = av[pb][j], h, l;
            if (bx == 0) na += v.x * v.x + v.y * v.y + v.z * v.z + v.w * v.w;
            h.x = __uint_as_float(__float_as_uint(v.x) & 0xFFFFE000u); l.x = v.x - h.x;
            h.y = __uint_as_float(__float_as_uint(v.y) & 0xFFFFE000u); l.y = v.y - h.y;
            h.z = __uint_as_float(__float_as_uint(v.z) & 0xFFFFE000u); l.z = v.z - h.z;
            h.w = __uint_as_float(__float_as_uint(v.w) & 0xFFFFE000u); l.w = v.w - h.w;
            *(float4*)(sb + OFF_AH + stsA[j]) = h;
            *(float4*)(sb + OFF_AL + stsA[j]) = l;
        }
#pragma unroll
        for (int q = 0; q < 8; q++) {
            float4 w = bv[pb][q], h, l;
            nb += w.x * w.x + w.y * w.y + w.z * w.z + w.w * w.w;
            h.x = __uint_as_float(__float_as_uint(w.x) & 0xFFFFE000u); l.x = w.x - h.x;
            h.y = __uint_as_float(__float_as_uint(w.y) & 0xFFFFE000u); l.y = w.y - h.y;
            h.z = __uint_as_float(__float_as_uint(w.z) & 0xFFFFE000u); l.z = w.z - h.z;
            h.w = __uint_as_float(__float_as_uint(w.w) & 0xFFFFE000u); l.w = w.w - h.w;
            *(float4*)(sb + OFF_BH + stsB[q]) = h;
            *(float4*)(sb + OFF_BL + stsB[q]) = l;
        }
        __syncthreads();

        // MMA issue for this stage: N=256, 4 K-steps x 3 terms
        if (wid == 0 && elect1()) {
            asm volatile("fence.proxy.async.shared::cta;" ::: "memory");
            uint32_t sbu = base + stg * STAGE_BYTES;
            uint64_t dAh = smem_desc(sbu + OFF_AH);
            uint64_t dAl = smem_desc(sbu + OFF_AL);
            uint64_t dBh = smem_desc(sbu + OFF_BH);
            uint64_t dBl = smem_desc(sbu + OFF_BL);
#pragma unroll
            for (int k = 0; k < 4; k++) mma_tf32_ss(tmem, dAh + 2 * k, dBh + 2 * k, (it > 0) || (k > 0));
#pragma unroll
            for (int k = 0; k < 4; k++) mma_tf32_ss(tmem, dAh + 2 * k, dBl + 2 * k, 1u);
#pragma unroll
            for (int k = 0; k < 4; k++) mma_tf32_ss(tmem, dAl + 2 * k, dBh + 2 * k, 1u);
            mma_commit(mb[stg]);
        }
    }

    // drain: tcgen05 ops complete in order -> wait for the last commit only
    mbar_wait(mb[(ntile - 1) & 1], ((ntile - 1) / NSTAGE) & 1);
    asm volatile("tcgen05.fence::after_thread_sync;" ::: "memory");

    // norm writeout
    g_cnp[s][n0 + rB] = nb;               // one thread per codebook row
    if (bx == 0) {
        float v = na + __shfl_xor_sync(0xFFFFFFFFu, na, 1);
        if ((t & 1) == 0) g_lnp[s][rA] = v;
    }

    // epilogue: TMEM D (128x256) -> g_part.
    {
        const int colb = (wid >> 2) * 128;
        const int m = (wid & 3) * 32 + lane;
        float* dst = &g_part[s][(size_t)m * C_SZ + n0 + colb];
        uint32_t dr[32];
#pragma unroll
        for (int blk = 0; blk < 4; blk++) {
            LDTM_X32(dr, tmem + colb + blk * 32);
            asm volatile("tcgen05.wait::ld.sync.aligned;" ::: "memory");
#pragma unroll
            for (int j = 0; j < 8; j++)
                ((float4*)(dst + blk * 32))[j] =
                    make_float4(__uint_as_float(dr[4 * j + 0]), __uint_as_float(dr[4 * j + 1]),
                                __uint_as_float(dr[4 * j + 2]), __uint_as_float(dr[4 * j + 3]));
        }
    }
    __syncthreads();
    if (wid == 0) tmem_dealloc(tmem, 256);

#else
    // ===== FFMA fallback (base pass; never selected at runtime; correct) ===
    const int rB = t;
    const float* bRow = Bm + (size_t)(n0 + rB) * D_SZ;
    const int klo = tile0 * BKA;
    const int khi = (tile0 + ntile) * BKA;

    float nb = 0.f;
    for (int k = klo; k < khi; k += 4) {
        float4 w = *(const float4*)(bRow + k);
        nb += w.x * w.x + w.y * w.y + w.z * w.z + w.w * w.w;
    }
    g_cnp[s][n0 + rB] = nb;

    if (bx == 0 && t < B_SZ) {
        const float* aRow = A + (size_t)t * D_SZ;
        float na = 0.f;
        for (int k = klo; k < khi; k += 4) {
            float4 v = *(const float4*)(aRow + k);
            na += v.x * v.x + v.y * v.y + v.z * v.z + v.w * v.w;
        }
        g_lnp[s][t] = na;
    }

    for (int m = 0; m < B_SZ; m++) {
        const float* aRow = A + (size_t)m * D_SZ;
        float acc = 0.f;
        for (int k = klo; k < khi; k += 4) {
            float4 v = *(const float4*)(aRow + k);
            float4 w = *(const float4*)(bRow + k);
            acc += v.x * w.x + v.y * w.y + v.z * w.z + v.w * w.w;
        }
        g_part[s][(size_t)m * C_SZ + n0 + rB] = acc;
    }
#endif
}

// ---------------------------------------------------------------------------
// Reduce: collapse split partials with full-chip parallelism.
// grid 517 x 256: i < 131072 -> dots; then cnorm (1024); then lnorm (128).
// ---------------------------------------------------------------------------
__global__ void reduce_kernel() {
    const int i = blockIdx.x * 256 + threadIdx.x;
    if (i < B_SZ * C_SZ) {
        float v = 0.f;
#pragma unroll
        for (int s = 0; s < SPLITS; s++) v += g_part[s][i];
        g_dot[i] = v;
    } else if (i < B_SZ * C_SZ + C_SZ) {
        const int c = i - B_SZ * C_SZ;
        float v = 0.f;
#pragma unroll
        for (int s = 0; s < SPLITS; s++) v += g_cnp[s][c];
        g_cnorm[c] = v;
    } else if (i < B_SZ * C_SZ + C_SZ + B_SZ) {
        const int b = i - B_SZ * C_SZ - C_SZ;
        float v = 0.f;
#pragma unroll
        for (int s = 0; s < SPLITS; s++) v += g_lnp[s][b];
        g_lnorm[b] = v;
    }
}

// ---------------------------------------------------------------------------
// Per-row: dist from reduced arrays, top-5 (lowest-index tie-break), softmax,
// outputs, usage scatter-add, stash for quantize.
// ---------------------------------------------------------------------------
__global__ void topk_kernel(float* __restrict__ out) {
    const int b   = blockIdx.x;
    const int tid = threadIdx.x;

    __shared__ float sd[C_SZ];
    __shared__ float rv[256];
    __shared__ int   ri[256];
    __shared__ float topd[TOPK];
    __shared__ int   topi[TOPK];

    const float ln = g_lnorm[b];
    for (int c = tid; c < C_SZ; c += 256) {
        float d2 = ln + g_cnorm[c] - 2.f * g_dot[b * C_SZ + c];
        sd[c] = sqrtf(fmaxf(d2, 0.f));
    }
    __syncthreads();

    for (int k = 0; k < TOPK; k++) {
        float best = FLT_MAX;
        int   bi   = C_SZ;
        for (int c = tid; c < C_SZ; c += 256) {
            float d = sd[c];
            if (d < best || (d == best && c < bi)) { best = d; bi = c; }
        }
        rv[tid] = best; ri[tid] = bi;
        __syncthreads();
        for (int s = 128; s > 0; s >>= 1) {
            if (tid < s) {
                float o = rv[tid + s]; int oi = ri[tid + s];
                if (o < rv[tid] || (o == rv[tid] && oi < ri[tid])) {
                    rv[tid] = o; ri[tid] = oi;
                }
            }
            __syncthreads();
        }
        if (tid == 0) {
            topd[k] = rv[0];
            topi[k] = ri[0];
            sd[ri[0]] = FLT_MAX;
        }
        __syncthreads();
    }

    if (tid == 0) {
        float m0 = topd[0];
        float e[TOPK], ssum = 0.f;
#pragma unroll
        for (int k = 0; k < TOPK; k++) {
            e[k] = expf(-(topd[k] - m0) / TEMP);
            ssum += e[k];
        }
        float inv = 1.f / ssum;
        out[OFF_IDX  + b] = (float)topi[0];
        out[OFF_DIST + b] = topd[0];
#pragma unroll
        for (int k = 0; k < TOPK; k++) {
            float w = e[k] * inv;
            atomicAdd(&out[OFF_USAGE + topi[k]], w);
            g_topw[b][k] = w;
            g_topi[b][k] = topi[k];
        }
    }
}

// ---------------------------------------------------------------------------
// quantized[b] = sum_k w[b][k] * codebook[idx[b][k]]   grid (B, 32 chunks)
// ---------------------------------------------------------------------------
__global__ void quant_kernel(const float* __restrict__ codebook,
                             float* __restrict__ out) {
    const int b     = blockIdx.x;
    const int chunk = blockIdx.y;
    const int tid   = threadIdx.x;
    __shared__ int   si[TOPK];
    __shared__ float sw[TOPK];
    if (tid < TOPK) { si[tid] = g_topi[b][tid]; sw[tid] = g_topw[b][tid]; }
    __syncthreads();

    const float4* cb = (const float4*)codebook;
    float4* outq = (float4*)(out + OFF_Q) + (size_t)b * D4;

    const float4* r0 = cb + (size_t)si[0] * D4;
    const float4* r1 = cb + (size_t)si[1] * D4;
    const float4* r2 = cb + (size_t)si[2] * D4;
    const float4* r3 = cb + (size_t)si[3] * D4;
    const float4* r4 = cb + (size_t)si[4] * D4;
    const float w0 = sw[0], w1 = sw[1], w2 = sw[2], w3 = sw[3], w4 = sw[4];

    const int p0 = chunk * (D4 / 32);
    const int p1 = p0 + (D4 / 32);
    for (int p = p0 + tid; p < p1; p += 256) {
        float4 v0 = r0[p], v1 = r1[p], v2 = r2[p], v3 = r3[p], v4 = r4[p];
        float4 r;
        r.x = w0 * v0.x + w1 * v1.x + w2 * v2.x + w3 * v3.x + w4 * v4.x;
        r.y = w0 * v0.y + w1 * v1.y + w2 * v2.y + w3 * v3.y + w4 * v4.y;
        r.z = w0 * v0.z + w1 * v1.z + w2 * v2.z + w3 * v3.z + w4 * v4.z;
        r.w = w0 * v0.w + w1 * v1.w + w2 * v2.w + w3 * v3.w + w4 * v4.w;
        outq[p] = r;
    }
}

// ---------------------------------------------------------------------------
extern "C" void kernel_launch(void* const* d_in, const int* in_sizes, int n_in,
                              void* d_out, int out_size) {
    const float* latent   = (const float*)d_in[0];
    const float* codebook = (const float*)d_in[1];
    const float* usage    = (const float*)d_in[2];
    float* out = (float*)d_out;

    cudaFuncSetAttribute((const void*)gemm_kernel,
                         cudaFuncAttributeMaxDynamicSharedMemorySize, DYN_SMEM);
    gemm_kernel<<<dim3(NB, SPLITS), 256, DYN_SMEM>>>(latent, codebook,
                                                     usage, out + OFF_USAGE);
    reduce_kernel<<<(B_SZ * C_SZ + C_SZ + B_SZ + 255) / 256, 256>>>();
    topk_kernel<<<B_SZ, 256>>>(out);
    quant_kernel<<<dim3(B_SZ, 32), 256>>>(codebook, out);
}